// round 3
// baseline (speedup 1.0000x reference)
#include <cuda_runtime.h>
#include <math.h>

#define BQ   8
#define DM   1024
#define VV   100279
#define BOTN 512
#define NHD  8
#define HDD  128
#define SS   2048
#define NCH  64
#define CHSZ 1567   // ceil(VV/64); 64*1567 = 100288 >= VV

// ---------------- device scratch (static: no allocations allowed) ----------------
__device__ float g_K[(size_t)BQ*NHD*SS*HDD];     // [b][h][s][hd]  64 MB
__device__ float g_V[(size_t)BQ*NHD*SS*HDD];     // 64 MB
__device__ float g_h[2*BQ*DM];                   // ping-pong hidden
__device__ float g_ctx[2*BQ*DM];                 // ping-pong ctx / prev_embed
__device__ float g_q[BQ*DM];
__device__ float g_attn[BQ*NHD*SS];
__device__ float g_attnout[BQ*DM];
__device__ float g_gelu[BQ*BOTN];
__device__ float g_logits[(size_t)BQ*VV];
__device__ float g_copy[(size_t)BQ*VV];          // zero-init; self-cleaned each step
__device__ float g_pm[BQ*NCH];
__device__ float g_ps[BQ*NCH];
__device__ float g_pgen[BQ];
__device__ float g_pv[BQ*NCH];
__device__ int   g_pi[BQ*NCH];

__device__ __forceinline__ float warp_sum(float v) {
#pragma unroll
    for (int o = 16; o; o >>= 1) v += __shfl_down_sync(0xffffffffu, v, o);
    return v;
}

// ---------------- init: copy hidden state into ping-pong slot 0 ----------------
__global__ void k_init(const float* __restrict__ hs) {
    int i = blockIdx.x * blockDim.x + threadIdx.x;
    if (i < BQ * DM) g_h[i] = hs[i];
}

// ---------------- generic linear: out[b, 0..nout) = x[b,:] @ w.T + bias --------
__global__ void k_linear(const float* __restrict__ x, const float* __restrict__ w,
                         const float* __restrict__ bias, float* __restrict__ out,
                         int nout) {
    int warp = (blockIdx.x * blockDim.x + threadIdx.x) >> 5;
    int lane = threadIdx.x & 31;
    int b = warp / nout, j = warp - b * nout;
    const float* xr = x + b * DM;
    const float* wr = w + (size_t)j * DM;
    float acc = 0.f;
    for (int d = lane; d < DM; d += 32) acc += xr[d] * wr[d];
    acc = warp_sum(acc);
    if (!lane) out[b * nout + j] = acc + bias[j];
}

// ---------------- scores: attn[b,h,s] = (q . k) * scale; also zeroes attnout ----
__global__ void k_scores() {
    int gt = blockIdx.x * blockDim.x + threadIdx.x;
    if (gt < BQ * DM) g_attnout[gt] = 0.f;   // cleared before k_av's atomics
    int warp = gt >> 5, lane = gt & 31;
    int b = warp >> 14;            // / (NHD*SS)
    int rem = warp & 16383;
    int h = rem >> 11, s = rem & 2047;
    const float* qr = g_q + b * DM + h * HDD;
    const float* kr = g_K + (((size_t)(b * NHD + h) * SS) + s) * HDD;
    float acc = 0.f;
#pragma unroll
    for (int d = lane; d < HDD; d += 32) acc += qr[d] * kr[d];
    acc = warp_sum(acc);
    if (!lane) g_attn[(b * NHD + h) * SS + s] = acc * 0.08838834764831845f; // 1/sqrt(128)
}

// ---------------- softmax over S per (b,h) + fused copy-dist scatter -----------
__global__ void k_softmax(const int* __restrict__ ids) {
    __shared__ float sm[SS];
    __shared__ float red[256];
    int bh = blockIdx.x, b = bh >> 3;
    int tid = threadIdx.x;
    float* row = g_attn + (size_t)bh * SS;
    float m = -INFINITY;
    for (int s = tid; s < SS; s += 256) { float v = row[s]; sm[s] = v; m = fmaxf(m, v); }
    red[tid] = m; __syncthreads();
    for (int o = 128; o; o >>= 1) { if (tid < o) red[tid] = fmaxf(red[tid], red[tid + o]); __syncthreads(); }
    m = red[0]; __syncthreads();
    float sum = 0.f;
    for (int s = tid; s < SS; s += 256) { float e = expf(sm[s] - m); sm[s] = e; sum += e; }
    red[tid] = sum; __syncthreads();
    for (int o = 128; o; o >>= 1) { if (tid < o) red[tid] += red[tid + o]; __syncthreads(); }
    float inv = 1.f / red[0];
    const int* idr = ids + b * SS;
    for (int s = tid; s < SS; s += 256) {
        float p = sm[s] * inv;
        row[s] = p;
        int id = idr[s];
        if (id >= 0) atomicAdd(&g_copy[(size_t)b * VV + id], p * 0.125f);  // mean over 8 heads
    }
}

// ---------------- attn @ V -> attnout (atomic partial sums over s-chunks) ------
__global__ void k_av() {
    int c = blockIdx.x & 15;
    int bh = blockIdx.x >> 4;
    int hd = threadIdx.x;
    const float* ar = g_attn + (size_t)bh * SS + c * 128;
    const float* vr = g_V + ((size_t)bh * SS + c * 128) * HDD + hd;
    float acc = 0.f;
#pragma unroll 4
    for (int s = 0; s < 128; s++) acc += ar[s] * vr[(size_t)s * HDD];
    int b = bh >> 3, h = bh & 7;
    atomicAdd(&g_attnout[b * DM + h * HDD + hd], acc);
}

// ---------------- vocab down-projection + exact GELU ---------------------------
__global__ void k_vocabdown(const float* __restrict__ h, const float* __restrict__ w,
                            const float* __restrict__ bias) {
    int warp = (blockIdx.x * 256 + threadIdx.x) >> 5, lane = threadIdx.x & 31;
    int b = warp >> 9, j = warp & 511;
    const float* xr = h + b * DM;
    const float* wr = w + (size_t)j * DM;
    float acc = 0.f;
    for (int d = lane; d < DM; d += 32) acc += xr[d] * wr[d];
    acc = warp_sum(acc);
    if (!lane) {
        float x = acc + bias[j];
        g_gelu[b * BOTN + j] = 0.5f * x * (1.f + erff(x * 0.70710678118654752f));
    }
}

// ---------------- logits[b,v] = gelu @ vocab_up_w.T ---------------------------
__global__ void k_vocabup(const float* __restrict__ wu) {
    __shared__ float gs[BQ * BOTN];   // 16 KB
    int tid = threadIdx.x;
    for (int i = tid; i < BQ * BOTN; i += 256) gs[i] = g_gelu[i];
    __syncthreads();
    int warp = tid >> 5, lane = tid & 31;
#pragma unroll
    for (int r = 0; r < 4; r++) {
        int v = blockIdx.x * 8 + warp + r * 25072;
        if (v < VV) {
            const float* wr = wu + (size_t)v * BOTN;
            float a0=0,a1=0,a2=0,a3=0,a4=0,a5=0,a6=0,a7=0;
            for (int j = lane; j < BOTN; j += 32) {
                float wv = wr[j];
                a0 += gs[j] * wv;            a1 += gs[BOTN + j] * wv;
                a2 += gs[2*BOTN + j] * wv;   a3 += gs[3*BOTN + j] * wv;
                a4 += gs[4*BOTN + j] * wv;   a5 += gs[5*BOTN + j] * wv;
                a6 += gs[6*BOTN + j] * wv;   a7 += gs[7*BOTN + j] * wv;
            }
            a0 = warp_sum(a0); a1 = warp_sum(a1); a2 = warp_sum(a2); a3 = warp_sum(a3);
            a4 = warp_sum(a4); a5 = warp_sum(a5); a6 = warp_sum(a6); a7 = warp_sum(a7);
            if (!lane) {
                g_logits[v]                 = a0;
                g_logits[(size_t)VV   + v]  = a1;
                g_logits[(size_t)2*VV + v]  = a2;
                g_logits[(size_t)3*VV + v]  = a3;
                g_logits[(size_t)4*VV + v]  = a4;
                g_logits[(size_t)5*VV + v]  = a5;
                g_logits[(size_t)6*VV + v]  = a6;
                g_logits[(size_t)7*VV + v]  = a7;
            }
        }
    }
}

// ---------------- partial softmax stats over V, plus p_gen in extra block ------
__global__ void k_reduceA(const float* __restrict__ h, const float* __restrict__ ctx,
                          const float* __restrict__ prev, const float* __restrict__ pw,
                          const float* __restrict__ pb) {
    if (blockIdx.x == 512) {
        int b = threadIdx.x >> 5, lane = threadIdx.x & 31;  // warp per batch
        float acc = 0.f;
        for (int i = lane; i < 3 * DM; i += 32) {
            float x = (i < DM) ? h[b * DM + i]
                    : (i < 2 * DM) ? ctx[b * DM + i - DM]
                    : prev[b * DM + i - 2 * DM];
            acc += x * pw[i];
        }
        acc = warp_sum(acc);
        if (!lane) g_pgen[b] = 1.f / (1.f + expf(-(acc + pb[0])));
        return;
    }
    __shared__ float red[256];
    int b = blockIdx.x >> 6, c = blockIdx.x & 63;
    int start = c * CHSZ, end = min(start + CHSZ, VV);
    const float* lr = g_logits + (size_t)b * VV;
    int tid = threadIdx.x;
    float m = -INFINITY;
    for (int i = start + tid; i < end; i += 256) m = fmaxf(m, lr[i]);
    red[tid] = m; __syncthreads();
    for (int o = 128; o; o >>= 1) { if (tid < o) red[tid] = fmaxf(red[tid], red[tid + o]); __syncthreads(); }
    m = red[0]; __syncthreads();
    float sum = 0.f;
    for (int i = start + tid; i < end; i += 256) sum += expf(lr[i] - m);
    red[tid] = sum; __syncthreads();
    for (int o = 128; o; o >>= 1) { if (tid < o) red[tid] += red[tid + o]; __syncthreads(); }
    if (!tid) { g_pm[b * NCH + c] = m; g_ps[b * NCH + c] = red[0]; }
}

// ---------------- final dist + partial argmax; self-clears copy buffer ---------
// NaN-transparent comparisons: for finite values identical to (f > best),
// but NaN updates instead of vanishing (diagnosability: never silently 0).
__global__ void k_final() {
    __shared__ float spm[NCH], sps[NCH], sMZ[2];
    __shared__ float bv[256];
    __shared__ int   bi[256];
    int b = blockIdx.x >> 6, c = blockIdx.x & 63;
    int tid = threadIdx.x;
    if (tid < NCH) { spm[tid] = g_pm[b * NCH + tid]; sps[tid] = g_ps[b * NCH + tid]; }
    __syncthreads();
    if (!tid) {
        float M = -INFINITY;
        for (int i = 0; i < NCH; i++) M = fmaxf(M, spm[i]);
        float Z = 0.f;
        for (int i = 0; i < NCH; i++) Z += sps[i] * expf(spm[i] - M);
        sMZ[0] = M; sMZ[1] = Z;
    }
    __syncthreads();
    float M  = sMZ[0];
    float pg = g_pgen[b];
    float a  = pg / sMZ[1];
    float om = 1.f - pg;
    int start = c * CHSZ, end = min(start + CHSZ, VV);
    float* lr = g_logits + (size_t)b * VV;
    float* cr = g_copy   + (size_t)b * VV;
    float best = -INFINITY; int bidx = start;
    for (int i = start + tid; i < end; i += 256) {
        float f = a * expf(lr[i] - M) + om * cr[i];
        cr[i] = 0.f;                      // clear for next step's scatter
        if (!(f <= best)) { best = f; bidx = i; }  // ascending i -> first-max kept
    }
    bv[tid] = best; bi[tid] = bidx; __syncthreads();
    for (int o = 128; o; o >>= 1) {
        if (tid < o) {
            float v2 = bv[tid + o]; int i2 = bi[tid + o];
            if (!(v2 <= bv[tid]) || (v2 == bv[tid] && i2 < bi[tid])) { bv[tid] = v2; bi[tid] = i2; }
        }
        __syncthreads();
    }
    if (!tid) { g_pv[b * NCH + c] = bv[0]; g_pi[b * NCH + c] = bi[0]; }
}

// ---------------- fused GRU update + token argmax combine ----------------------
// NOTE: output written as FLOAT (harness __output__ dtype is float32; int bit
// patterns of small tokens are denormals ~1e-40 -> the exact rel_err=1.0 we saw).
__global__ void k_gru(const float* __restrict__ h, const float* __restrict__ ctx,
                      float* __restrict__ hout,
                      const float* __restrict__ wih, const float* __restrict__ whh,
                      const float* __restrict__ wch, const float* __restrict__ bih,
                      const float* __restrict__ bhh,
                      float* __restrict__ out, int t, int steps) {
    int warp = (blockIdx.x * 256 + threadIdx.x) >> 5, lane = threadIdx.x & 31;
    int b = warp >> 10, j = warp & 1023;
    const float* cx = ctx + b * DM;
    const float* hx = h + b * DM;
    const float* wi_r = wih + (size_t)j * DM;
    const float* wi_z = wih + (size_t)(DM + j) * DM;
    const float* wi_n = wih + (size_t)(2 * DM + j) * DM;
    const float* wh_r = whh + (size_t)j * DM;
    const float* wh_z = whh + (size_t)(DM + j) * DM;
    const float* wh_n = whh + (size_t)(2 * DM + j) * DM;
    const float* wc_r = wch + (size_t)j * DM;
    const float* wc_z = wch + (size_t)(DM + j) * DM;
    const float* wc_n = wch + (size_t)(2 * DM + j) * DM;
    float ir=0, iz=0, inn=0, hr=0, hz=0, hn=0, cr=0, cz=0, cn=0;
    for (int d = lane; d < DM; d += 32) {
        float cv = cx[d], hv = hx[d];
        ir  += cv * wi_r[d]; iz += cv * wi_z[d]; inn += cv * wi_n[d];
        hr  += hv * wh_r[d]; hz += hv * wh_z[d]; hn  += hv * wh_n[d];
        cr  += cv * wc_r[d]; cz += cv * wc_z[d]; cn  += cv * wc_n[d];
    }
    ir = warp_sum(ir); iz = warp_sum(iz); inn = warp_sum(inn);
    hr = warp_sum(hr); hz = warp_sum(hz); hn  = warp_sum(hn);
    cr = warp_sum(cr); cz = warp_sum(cz); cn  = warp_sum(cn);
    if (!lane) {
        float r = 1.f / (1.f + expf(-(ir + bih[j]      + hr + bhh[j]      + cr)));
        float z = 1.f / (1.f + expf(-(iz + bih[DM + j] + hz + bhh[DM + j] + cz)));
        float n = tanhf(inn + bih[2 * DM + j] + cn + r * (hn + bhh[2 * DM + j]));
        hout[b * DM + j] = (1.f - z) * n + z * hx[j];
    }
    // token combine (reads k_final's partials); NaN-transparent
    if (blockIdx.x == 0 && threadIdx.x < 8) {
        int bb = threadIdx.x;
        float best = g_pv[bb * NCH];
        int bidx = g_pi[bb * NCH];
        for (int c = 1; c < NCH; c++) {
            float v = g_pv[bb * NCH + c];
            if (!(v <= best)) { best = v; bidx = g_pi[bb * NCH + c]; }
        }
        out[bb * steps + t] = (float)bidx;
    }
}

// ---------------- one-time K/V projection GEMM ---------------------------------
__global__ void k_kvgemm(const float* __restrict__ A, const float* __restrict__ W,
                         const float* __restrict__ bias) {
    __shared__ float As[16][128];
    __shared__ float Bs[16][128];
    int tid = threadIdx.x;
    int bm = blockIdx.y * 128, bn = blockIdx.x * 128;
    int tr = tid >> 4, tc = tid & 15;
    float acc[8][8];
#pragma unroll
    for (int i = 0; i < 8; i++)
#pragma unroll
        for (int j = 0; j < 8; j++) acc[i][j] = 0.f;
    int lr = tid >> 2;
    int lk = (tid & 3) * 4;
    const float* Ag = A + (size_t)(bm + lr) * 1024 + lk;
    const float* Wg = W + (size_t)(bn + lr) * 1024 + lk;
    for (int kt = 0; kt < 1024; kt += 16) {
        float4 a0 = *(const float4*)(Ag + kt);
        float4 a1 = *(const float4*)(Ag + (size_t)64 * 1024 + kt);
        float4 b0 = *(const float4*)(Wg + kt);
        float4 b1 = *(const float4*)(Wg + (size_t)64 * 1024 + kt);
        As[lk+0][lr] = a0.x; As[lk+1][lr] = a0.y; As[lk+2][lr] = a0.z; As[lk+3][lr] = a0.w;
        As[lk+0][lr+64] = a1.x; As[lk+1][lr+64] = a1.y; As[lk+2][lr+64] = a1.z; As[lk+3][lr+64] = a1.w;
        Bs[lk+0][lr] = b0.x; Bs[lk+1][lr] = b0.y; Bs[lk+2][lr] = b0.z; Bs[lk+3][lr] = b0.w;
        Bs[lk+0][lr+64] = b1.x; Bs[lk+1][lr+64] = b1.y; Bs[lk+2][lr+64] = b1.z; Bs[lk+3][lr+64] = b1.w;
        __syncthreads();
#pragma unroll
        for (int kk = 0; kk < 16; kk++) {
            float ra[8], rb[8];
#pragma unroll
            for (int i = 0; i < 8; i++) ra[i] = As[kk][tr + 16 * i];
#pragma unroll
            for (int j = 0; j < 8; j++) rb[j] = Bs[kk][tc + 16 * j];
#pragma unroll
            for (int i = 0; i < 8; i++)
#pragma unroll
                for (int j = 0; j < 8; j++) acc[i][j] += ra[i] * rb[j];
        }
        __syncthreads();
    }
#pragma unroll
    for (int i = 0; i < 8; i++) {
        int m = bm + tr + 16 * i;
        int b = m >> 11, s = m & 2047;
#pragma unroll
        for (int j = 0; j < 8; j++) {
            int n = bn + tc + 16 * j;
            float val = acc[i][j] + bias[n];
            if (n < DM)
                g_K[((size_t)(b * NHD + (n >> 7)) * SS + s) * HDD + (n & 127)] = val;
            else {
                int n2 = n - DM;
                g_V[((size_t)(b * NHD + (n2 >> 7)) * SS + s) * HDD + (n2 & 127)] = val;
            }
        }
    }
}

// ---------------- host orchestration -------------------------------------------
extern "C" void kernel_launch(void* const* d_in, const int* in_sizes, int n_in,
                              void* d_out, int out_size) {
    const float* hidden  = (const float*)d_in[0];
    const float* context = (const float*)d_in[1];
    const int*   ids     = (const int*)d_in[2];
    // Auto-detect whether the scalar max_tokens occupies d_in[3]:
    // if present, in_sizes[3] == 1; vocab_down_w (524288 elems) can never be 1.
    int base = (in_sizes[3] == 1) ? 4 : 3;
    const float* vdw = (const float*)d_in[base + 0];
    const float* vdb = (const float*)d_in[base + 1];
    const float* vuw = (const float*)d_in[base + 2];
    const float* ipw = (const float*)d_in[base + 3];
    const float* ipb = (const float*)d_in[base + 4];
    const float* opw = (const float*)d_in[base + 5];
    const float* opb = (const float*)d_in[base + 6];
    const float* pgw = (const float*)d_in[base + 7];
    const float* pgb = (const float*)d_in[base + 8];
    const float* wih = (const float*)d_in[base + 9];
    const float* whh = (const float*)d_in[base + 10];
    const float* wch = (const float*)d_in[base + 11];
    const float* bih = (const float*)d_in[base + 12];
    const float* bhh = (const float*)d_in[base + 13];
    const float* inw = (const float*)d_in[base + 14];
    const float* inb = (const float*)d_in[base + 15];
    float* out = (float*)d_out;
    int steps = out_size / BQ;

    float *hbase, *cbase, *qbase, *aobase;
    cudaGetSymbolAddress((void**)&hbase, g_h);
    cudaGetSymbolAddress((void**)&cbase, g_ctx);
    cudaGetSymbolAddress((void**)&qbase, g_q);
    cudaGetSymbolAddress((void**)&aobase, g_attnout);

    k_init<<<32, 256>>>(hidden);
    // prev_embed(0) = hidden @ input_proj.T + b  -> ctx slot 1
    k_linear<<<1024, 256>>>(hidden, inw, inb, cbase + BQ * DM, DM);
    // K/V projection: W rows 1024..3071 of in_proj (wk|wv)
    k_kvgemm<<<dim3(16, 128), 256>>>(context, ipw + 1024 * 1024, ipb + 1024);

    for (int t = 0; t < steps; t++) {
        float* h_in    = hbase + (t & 1) * BQ * DM;
        float* h_out   = hbase + ((t + 1) & 1) * BQ * DM;
        float* ctx_cur = cbase + (t & 1) * BQ * DM;
        float* prev    = cbase + ((t + 1) & 1) * BQ * DM;

        k_linear<<<1024, 256>>>(h_in, ipw, ipb, qbase, DM);        // q = h @ wq.T + bq
        k_scores<<<16384, 256>>>();                                // scores (+ zero attnout)
        k_softmax<<<64, 256>>>(ids);                               // softmax + copy scatter
        k_av<<<1024, 128>>>();                                     // attn @ V
        k_linear<<<1024, 256>>>(aobase, opw, opb, ctx_cur, DM);    // out_proj
        k_vocabdown<<<512, 256>>>(h_in, vdw, vdb);                 // down + gelu
        k_vocabup<<<3134, 256>>>(vuw);                             // big vocab matmul
        k_reduceA<<<513, 256>>>(h_in, ctx_cur, prev, pgw, pgb);    // softmax stats + p_gen
        k_final<<<512, 256>>>();                                   // final dist + argmax partials
        k_gru<<<1024, 256>>>(h_in, ctx_cur, h_out, wih, whh, wch,
                             bih, bhh, out, t, steps);             // GRU + token write
    }
}

// round 4
// speedup vs baseline: 1.1688x; 1.1688x over previous
#include <cuda_runtime.h>
#include <math.h>

#define BQ   8
#define DM   1024
#define VV   100279
#define BOTN 512
#define NHD  8
#define HDD  128
#define SS   2048
#define NCH  64
#define CHSZ 1567   // ceil(VV/64)

// ---------------- device scratch ----------------
__device__ float g_K[(size_t)BQ*NHD*SS*HDD];
__device__ float g_V[(size_t)BQ*NHD*SS*HDD];
__device__ float g_h[2*BQ*DM];
__device__ float g_q[BQ*DM];
__device__ float g_attn[BQ*NHD*SS];
__device__ float g_ao[BQ*DM];
__device__ float g_gelu[BQ*BOTN];
__device__ float g_gh[BQ*3*DM];
__device__ float g_logits[(size_t)BQ*VV];
__device__ float g_copy[(size_t)BQ*VV];          // zero-init; self-cleaned
__device__ float g_Wihp[(size_t)3*DM*DM];        // wih @ opw
__device__ float g_Wchp[(size_t)3*DM*DM];        // wch @ opw
__device__ float g_bihp[3*DM];
__device__ float g_bchp[3*DM];
__device__ float g_Vw2[BQ*NHD*SS];
__device__ float g_Vw3[BQ*NHD*SS];
__device__ float g_u[DM];                        // inw^T w3
__device__ float g_w2p[DM];                      // opw^T w2
__device__ float g_w3p[DM];                      // opw^T w3
__device__ float g_c[3];                         // c2=w2.opb, c3=w3.opb, s1=w3.inb
__device__ float g_hpart[BQ];
__device__ float g_pacc2[BQ];
__device__ float g_pacc3[2][BQ];
__device__ float g_pm[BQ*NCH];
__device__ float g_ps[BQ*NCH];
__device__ float g_pv[BQ*NCH];
__device__ int   g_pi[BQ*NCH];

__device__ __forceinline__ float warp_sum(float v) {
#pragma unroll
    for (int o = 16; o; o >>= 1) v += __shfl_down_sync(0xffffffffu, v, o);
    return v;
}
__device__ __forceinline__ float dot4(float4 a, float4 b) {
    return a.x*b.x + a.y*b.y + a.z*b.z + a.w*b.w;
}

// ---------------- init ----------------
__global__ void k_init(const float* __restrict__ hs) {
    int i = blockIdx.x * blockDim.x + threadIdx.x;
    if (i < BQ * DM) g_h[i] = hs[i];
}

// ---------------- one-time K/V projection GEMM (A@W^T + bias) ----------------
__global__ void k_kvgemm(const float* __restrict__ A, const float* __restrict__ W,
                         const float* __restrict__ bias) {
    __shared__ float As[16][128];
    __shared__ float Bs[16][128];
    int tid = threadIdx.x;
    int bm = blockIdx.y * 128, bn = blockIdx.x * 128;
    int tr = tid >> 4, tc = tid & 15;
    float acc[8][8];
#pragma unroll
    for (int i = 0; i < 8; i++)
#pragma unroll
        for (int j = 0; j < 8; j++) acc[i][j] = 0.f;
    int lr = tid >> 2;
    int lk = (tid & 3) * 4;
    const float* Ag = A + (size_t)(bm + lr) * DM + lk;
    const float* Wg = W + (size_t)(bn + lr) * DM + lk;
    for (int kt = 0; kt < DM; kt += 16) {
        float4 a0 = *(const float4*)(Ag + kt);
        float4 a1 = *(const float4*)(Ag + (size_t)64 * DM + kt);
        float4 b0 = *(const float4*)(Wg + kt);
        float4 b1 = *(const float4*)(Wg + (size_t)64 * DM + kt);
        As[lk+0][lr] = a0.x; As[lk+1][lr] = a0.y; As[lk+2][lr] = a0.z; As[lk+3][lr] = a0.w;
        As[lk+0][lr+64] = a1.x; As[lk+1][lr+64] = a1.y; As[lk+2][lr+64] = a1.z; As[lk+3][lr+64] = a1.w;
        Bs[lk+0][lr] = b0.x; Bs[lk+1][lr] = b0.y; Bs[lk+2][lr] = b0.z; Bs[lk+3][lr] = b0.w;
        Bs[lk+0][lr+64] = b1.x; Bs[lk+1][lr+64] = b1.y; Bs[lk+2][lr+64] = b1.z; Bs[lk+3][lr+64] = b1.w;
        __syncthreads();
#pragma unroll
        for (int kk = 0; kk < 16; kk++) {
            float ra[8], rb[8];
#pragma unroll
            for (int i = 0; i < 8; i++) ra[i] = As[kk][tr + 16 * i];
#pragma unroll
            for (int j = 0; j < 8; j++) rb[j] = Bs[kk][tc + 16 * j];
#pragma unroll
            for (int i = 0; i < 8; i++)
#pragma unroll
                for (int j = 0; j < 8; j++) acc[i][j] += ra[i] * rb[j];
        }
        __syncthreads();
    }
#pragma unroll
    for (int i = 0; i < 8; i++) {
        int m = bm + tr + 16 * i;
        int b = m >> 11, s = m & 2047;
#pragma unroll
        for (int j = 0; j < 8; j++) {
            int n = bn + tc + 16 * j;
            float val = acc[i][j] + bias[n];
            if (n < DM)
                g_K[((size_t)(b * NHD + (n >> 7)) * SS + s) * HDD + (n & 127)] = val;
            else {
                int n2 = n - DM;
                g_V[((size_t)(b * NHD + (n2 >> 7)) * SS + s) * HDD + (n2 & 127)] = val;
            }
        }
    }
}

// ---------------- one-time C = A @ B (A[M,1024], B[1024,1024]) ----------------
__global__ void k_mmAB(const float* __restrict__ A, const float* __restrict__ B,
                       float* __restrict__ C) {
    __shared__ float As[16][128];
    __shared__ float Bs[16][128];
    int tid = threadIdx.x;
    int bm = blockIdx.y * 128, bn = blockIdx.x * 128;
    int tr = tid >> 4, tc = tid & 15;
    float acc[8][8];
#pragma unroll
    for (int i = 0; i < 8; i++)
#pragma unroll
        for (int j = 0; j < 8; j++) acc[i][j] = 0.f;
    int lr = tid >> 2;
    int lk = (tid & 3) * 4;
    int bkr = tid >> 4;            // 0..15
    int bnc = (tid & 15) * 4;      // 0..60
    const float* Ag = A + (size_t)(bm + lr) * DM + lk;
    for (int kt = 0; kt < DM; kt += 16) {
        float4 a0 = *(const float4*)(Ag + kt);
        float4 a1 = *(const float4*)(Ag + (size_t)64 * DM + kt);
        As[lk+0][lr] = a0.x; As[lk+1][lr] = a0.y; As[lk+2][lr] = a0.z; As[lk+3][lr] = a0.w;
        As[lk+0][lr+64] = a1.x; As[lk+1][lr+64] = a1.y; As[lk+2][lr+64] = a1.z; As[lk+3][lr+64] = a1.w;
        float4 b0 = *(const float4*)(B + (size_t)(kt + bkr) * DM + bn + bnc);
        float4 b1 = *(const float4*)(B + (size_t)(kt + bkr) * DM + bn + bnc + 64);
        Bs[bkr][bnc+0] = b0.x; Bs[bkr][bnc+1] = b0.y; Bs[bkr][bnc+2] = b0.z; Bs[bkr][bnc+3] = b0.w;
        Bs[bkr][bnc+64] = b1.x; Bs[bkr][bnc+65] = b1.y; Bs[bkr][bnc+66] = b1.z; Bs[bkr][bnc+67] = b1.w;
        __syncthreads();
#pragma unroll
        for (int kk = 0; kk < 16; kk++) {
            float ra[8], rb[8];
#pragma unroll
            for (int i = 0; i < 8; i++) ra[i] = As[kk][tr + 16 * i];
#pragma unroll
            for (int j = 0; j < 8; j++) rb[j] = Bs[kk][tc + 16 * j];
#pragma unroll
            for (int i = 0; i < 8; i++)
#pragma unroll
                for (int j = 0; j < 8; j++) acc[i][j] += ra[i] * rb[j];
        }
        __syncthreads();
    }
#pragma unroll
    for (int i = 0; i < 8; i++)
#pragma unroll
        for (int j = 0; j < 8; j++)
            C[(size_t)(bm + tr + 16 * i) * DM + bn + tc + 16 * j] = acc[i][j];
}

// ---------------- one-time: u = inw^T w3, w2p = opw^T w2, w3p = opw^T w3, scalars ----
__global__ void k_prep(const float* __restrict__ inw, const float* __restrict__ inb,
                       const float* __restrict__ opw, const float* __restrict__ opb,
                       const float* __restrict__ pgw) {
    int blk = blockIdx.x, tid = threadIdx.x;
    if (blk < 12) {
        int which = blk >> 2;                 // 0:u 1:w2p 2:w3p
        int d = (blk & 3) * 256 + tid;
        const float* Wm = which ? opw : inw;
        const float* vec = (which == 1) ? pgw + DM : pgw + 2 * DM;
        float acc = 0.f;
        for (int k = 0; k < DM; k++) acc += vec[k] * Wm[(size_t)k * DM + d];
        if (which == 0) g_u[d] = acc;
        else if (which == 1) g_w2p[d] = acc;
        else g_w3p[d] = acc;
    } else {
        int w = tid >> 5, lane = tid & 31;
        if (w < 3) {
            const float* vec = (w == 0) ? pgw + DM : pgw + 2 * DM;
            const float* src = (w == 2) ? inb : opb;
            float acc = 0.f;
            for (int k = lane; k < DM; k += 32) acc += vec[k] * src[k];
            acc = warp_sum(acc);
            if (!lane) g_c[w] = acc;          // c2, c3, s1
        }
    }
}

// ---------------- one-time: prev0 partial -> pacc3[1] ----------------
__global__ void k_prev0(const float* __restrict__ h0) {
    int w = threadIdx.x >> 5, lane = threadIdx.x & 31;
    if (w < 8) {
        float acc = 0.f;
        for (int d = lane; d < DM; d += 32) acc += h0[w * DM + d] * g_u[d];
        acc = warp_sum(acc);
        if (!lane) g_pacc3[1][w] = acc + g_c[2] - g_c[1];   // prev0.w3 - c3
    }
}

// ---------------- one-time: bihp/bchp ----------------
__global__ void k_bias2(const float* __restrict__ wih, const float* __restrict__ wch,
                        const float* __restrict__ bih, const float* __restrict__ opb) {
    int w = (blockIdx.x * 256 + threadIdx.x) >> 5, lane = threadIdx.x & 31;
    if (w >= 6144) return;
    int type = w >= 3072 ? 1 : 0;
    int j = w - type * 3072;
    const float* row = (type ? wch : wih) + (size_t)j * DM;
    float acc = 0.f;
    for (int d = lane; d < DM; d += 32) acc += row[d] * opb[d];
    acc = warp_sum(acc);
    if (!lane) { if (type) g_bchp[j] = acc; else g_bihp[j] = acc + bih[j]; }
}

// ---------------- one-time: Vw2/Vw3 ----------------
__global__ void k_vw23() {
    int gw = (blockIdx.x * 256 + threadIdx.x) >> 5, lane = threadIdx.x & 31;
    int r0 = gw * 32;
    for (int rr = 0; rr < 32; rr++) {
        int r = r0 + rr;                        // [0, 131072)
        int h = (r >> 11) & 7;
        float4 a  = ((const float4*)(g_V + (size_t)r * HDD))[lane];
        float4 w2 = *(const float4*)(g_w2p + h * HDD + lane * 4);
        float4 w3 = *(const float4*)(g_w3p + h * HDD + lane * 4);
        float d2 = warp_sum(dot4(a, w2));
        float d3 = warp_sum(dot4(a, w3));
        if (!lane) { g_Vw2[r] = d2; g_Vw3[r] = d3; }
    }
}

// ---------------- L1: q, gelu, gh, hpart from h (+ token combine t-1) ----------
__global__ void k_hstage(const float* __restrict__ h,
                         const float* __restrict__ ipw, const float* __restrict__ ipb,
                         const float* __restrict__ vdw, const float* __restrict__ vdb,
                         const float* __restrict__ whh, const float* __restrict__ bhh,
                         const float* __restrict__ pgw,
                         float* __restrict__ out, int t, int steps) {
    __shared__ float hs[BQ * DM];
    int tid = threadIdx.x;
    if (blockIdx.x == 0 && tid < 8 && t > 0) {
        int bb = tid;
        float best = g_pv[bb * NCH];
        int bidx = g_pi[bb * NCH];
        for (int c = 1; c < NCH; c++) {
            float v = g_pv[bb * NCH + c];
            if (!(v <= best)) { best = v; bidx = g_pi[bb * NCH + c]; }
        }
        out[bb * steps + (t - 1)] = (float)bidx;
    }
    for (int i = tid; i < BQ * DM / 4; i += 256)
        ((float4*)hs)[i] = ((const float4*)h)[i];
    __syncthreads();
    int job = blockIdx.x * 8 + (tid >> 5);
    int lane = tid & 31;
    if (job >= 4609) return;
    const float* wrow;
    if (job < 1024)       wrow = ipw + (size_t)job * DM;
    else if (job < 1536)  wrow = vdw + (size_t)(job - 1024) * DM;
    else if (job < 4608)  wrow = whh + (size_t)(job - 1536) * DM;
    else                  wrow = pgw;
    const float4* w4p = (const float4*)wrow;
    const float4* h4 = (const float4*)hs;
    float acc[8] = {};
#pragma unroll
    for (int i = 0; i < 8; i++) {
        int f = i * 32 + lane;
        float4 w4 = w4p[f];
#pragma unroll
        for (int b = 0; b < 8; b++) {
            float4 a4 = h4[b * 256 + f];
            acc[b] += dot4(w4, a4);
        }
    }
#pragma unroll
    for (int b = 0; b < 8; b++) acc[b] = warp_sum(acc[b]);
    if (lane) return;
    if (job < 1024) {
        float bias = ipb[job];
#pragma unroll
        for (int b = 0; b < 8; b++) g_q[b * DM + job] = acc[b] + bias;
    } else if (job < 1536) {
        int j = job - 1024;
        float bias = vdb[j];
#pragma unroll
        for (int b = 0; b < 8; b++) {
            float x = acc[b] + bias;
            g_gelu[b * BOTN + j] = 0.5f * x * (1.f + erff(x * 0.70710678118654752f));
        }
    } else if (job < 4608) {
        int j = job - 1536;
        float bias = bhh[j];
#pragma unroll
        for (int b = 0; b < 8; b++) g_gh[b * 3 * DM + j] = acc[b] + bias;
    } else {
#pragma unroll
        for (int b = 0; b < 8; b++) g_hpart[b] = acc[b];
    }
}

// ---------------- L2: scores + zero + vocabup ----------------
__global__ void k_wide1(const float* __restrict__ vuw, int t) {
    int bx = blockIdx.x, tid = threadIdx.x;
    if (bx < 512) {
        int b = bx >> 6, hh = (bx >> 3) & 7, ch = bx & 7;
        int warp = tid >> 5, lane = tid & 31;
        float4 q4 = *(const float4*)(g_q + b * DM + hh * HDD + lane * 4);
        int bh = b * 8 + hh;
        const float4* K4 = (const float4*)(g_K + (size_t)bh * SS * HDD);
        int s0 = ch * 256 + warp * 32;
#pragma unroll 4
        for (int ss = 0; ss < 32; ss++) {
            int s = s0 + ss;
            float d = warp_sum(dot4(K4[s * 32 + lane], q4));
            if (!lane) g_attn[bh * SS + s] = d * 0.08838834764831845f;
        }
        return;
    }
    if (bx == 512) {
        for (int i = tid; i < BQ * DM; i += 256) g_ao[i] = 0.f;
        if (tid < 8) { g_pacc2[tid] = 0.f; g_pacc3[t & 1][tid] = 0.f; }
        return;
    }
    __shared__ float gs[BQ * BOTN];
    for (int i = tid; i < BQ * BOTN / 4; i += 256)
        ((float4*)gs)[i] = ((const float4*)g_gelu)[i];
    __syncthreads();
    int v = (bx - 513) * 8 + (tid >> 5);
    int lane = tid & 31;
    if (v >= VV) return;
    const float4* w4p = (const float4*)(vuw + (size_t)v * BOTN);
    const float4* g4 = (const float4*)gs;
    float4 acc4[8];
#pragma unroll
    for (int b = 0; b < 8; b++) acc4[b] = make_float4(0.f, 0.f, 0.f, 0.f);
#pragma unroll
    for (int i = 0; i < 4; i++) {
        int f = i * 32 + lane;
        float4 w4 = w4p[f];
#pragma unroll
        for (int b = 0; b < 8; b++) {
            float4 a4 = g4[b * 128 + f];
            acc4[b].x += w4.x * a4.x; acc4[b].y += w4.y * a4.y;
            acc4[b].z += w4.z * a4.z; acc4[b].w += w4.w * a4.w;
        }
    }
#pragma unroll
    for (int b = 0; b < 8; b++) {
        float s = warp_sum(acc4[b].x + acc4[b].y + acc4[b].z + acc4[b].w);
        if (!lane) g_logits[(size_t)b * VV + v] = s;
    }
}

// ---------------- L3: softmax+scatter+pgen dots  |  logit stats chunks ----------
__global__ void k_wide2(const int* __restrict__ ids, int t) {
    __shared__ float sm[SS];
    __shared__ float red[256];
    int bx = blockIdx.x, tid = threadIdx.x;
    if (bx < 64) {
        int bh = bx, b = bh >> 3;
        float* row = g_attn + (size_t)bh * SS;
        float m = -INFINITY;
        for (int s = tid; s < SS; s += 256) { float v = row[s]; sm[s] = v; m = fmaxf(m, v); }
        red[tid] = m; __syncthreads();
        for (int o = 128; o; o >>= 1) { if (tid < o) red[tid] = fmaxf(red[tid], red[tid + o]); __syncthreads(); }
        m = red[0]; __syncthreads();
        float sum = 0.f;
        for (int s = tid; s < SS; s += 256) { float e = expf(sm[s] - m); sm[s] = e; sum += e; }
        red[tid] = sum; __syncthreads();
        for (int o = 128; o; o >>= 1) { if (tid < o) red[tid] += red[tid + o]; __syncthreads(); }
        float inv = 1.f / red[0];
        __syncthreads();
        const int* idr = ids + b * SS;
        float acc2 = 0.f, acc3 = 0.f;
        for (int s = tid; s < SS; s += 256) {
            float p = sm[s] * inv;
            row[s] = p;
            acc2 += p * g_Vw2[bh * SS + s];
            acc3 += p * g_Vw3[bh * SS + s];
            int id = idr[s];
            if (id >= 0) atomicAdd(&g_copy[(size_t)b * VV + id], p * 0.125f);
        }
        red[tid] = acc2; __syncthreads();
        for (int o = 128; o; o >>= 1) { if (tid < o) red[tid] += red[tid + o]; __syncthreads(); }
        if (!tid) atomicAdd(&g_pacc2[b], red[0]);
        __syncthreads();
        red[tid] = acc3; __syncthreads();
        for (int o = 128; o; o >>= 1) { if (tid < o) red[tid] += red[tid + o]; __syncthreads(); }
        if (!tid) atomicAdd(&g_pacc3[t & 1][b], red[0]);
        return;
    }
    int cc = bx - 64;
    int b = cc >> 6, c = cc & 63;
    int start = c * CHSZ, end = min(start + CHSZ, VV);
    const float* lr = g_logits + (size_t)b * VV;
    float m = -INFINITY;
    for (int i = start + tid; i < end; i += 256) m = fmaxf(m, lr[i]);
    red[tid] = m; __syncthreads();
    for (int o = 128; o; o >>= 1) { if (tid < o) red[tid] = fmaxf(red[tid], red[tid + o]); __syncthreads(); }
    m = red[0]; __syncthreads();
    float sum = 0.f;
    for (int i = start + tid; i < end; i += 256) sum += expf(lr[i] - m);
    red[tid] = sum; __syncthreads();
    for (int o = 128; o; o >>= 1) { if (tid < o) red[tid] += red[tid + o]; __syncthreads(); }
    if (!tid) { g_pm[b * NCH + c] = m; g_ps[b * NCH + c] = red[0]; }
}

// ---------------- L4: attn @ V -> ao ----------------
__global__ void k_avk() {
    __shared__ float sa[256];
    __shared__ float sacc[8 * 128];
    int bx = blockIdx.x, tid = threadIdx.x;
    int b = bx >> 6, hh = (bx >> 3) & 7, ch = bx & 7, bh = b * 8 + hh;
    sa[tid] = g_attn[bh * SS + ch * 256 + tid];
    __syncthreads();
    int warp = tid >> 5, lane = tid & 31;
    const float4* V4 = (const float4*)(g_V + (size_t)bh * SS * HDD);
    float4 acc = make_float4(0.f, 0.f, 0.f, 0.f);
    int s0 = ch * 256 + warp * 32;
#pragma unroll 4
    for (int ss = 0; ss < 32; ss++) {
        float a = sa[warp * 32 + ss];
        float4 v4 = V4[(s0 + ss) * 32 + lane];
        acc.x += a * v4.x; acc.y += a * v4.y; acc.z += a * v4.z; acc.w += a * v4.w;
    }
    float* strip = sacc + warp * 128 + lane * 4;
    strip[0] = acc.x; strip[1] = acc.y; strip[2] = acc.z; strip[3] = acc.w;
    __syncthreads();
    if (tid < 128) {
        float s = 0.f;
#pragma unroll
        for (int w = 0; w < 8; w++) s += sacc[w * 128 + tid];
        atomicAdd(&g_ao[b * DM + hh * HDD + tid], s);
    }
}

// ---------------- L5: final argmax (+pgen inline)  |  GRU ----------------
__global__ void k_tail(const float* __restrict__ h, float* __restrict__ hout,
                       const float* __restrict__ pgb, int t) {
    int bx = blockIdx.x, tid = threadIdx.x;
    if (bx < 512) {
        __shared__ float spm[NCH], sps[NCH], sMZ[2];
        __shared__ float bv[256];
        __shared__ int bi[256];
        int b = bx >> 6, c = bx & 63;
        if (tid < NCH) { spm[tid] = g_pm[b * NCH + tid]; sps[tid] = g_ps[b * NCH + tid]; }
        __syncthreads();
        if (!tid) {
            float M = -INFINITY;
            for (int i = 0; i < NCH; i++) M = fmaxf(M, spm[i]);
            float Z = 0.f;
            for (int i = 0; i < NCH; i++) Z += sps[i] * expf(spm[i] - M);
            sMZ[0] = M; sMZ[1] = Z;
        }
        __syncthreads();
        float M = sMZ[0];
        float pg = 1.f / (1.f + expf(-(g_hpart[b] + g_pacc2[b] + g_c[0]
                                       + g_pacc3[(t + 1) & 1][b] + g_c[1] + pgb[0])));
        float a = pg / sMZ[1];
        float om = 1.f - pg;
        int start = c * CHSZ, end = min(start + CHSZ, VV);
        float* lr = g_logits + (size_t)b * VV;
        float* cr = g_copy + (size_t)b * VV;
        float best = -INFINITY; int bidx = start;
        for (int i = start + tid; i < end; i += 256) {
            float f = a * expf(lr[i] - M) + om * cr[i];
            cr[i] = 0.f;
            if (!(f <= best)) { best = f; bidx = i; }
        }
        bv[tid] = best; bi[tid] = bidx; __syncthreads();
        for (int o = 128; o; o >>= 1) {
            if (tid < o) {
                float v2 = bv[tid + o]; int i2 = bi[tid + o];
                if (!(v2 <= bv[tid]) || (v2 == bv[tid] && i2 < bi[tid])) { bv[tid] = v2; bi[tid] = i2; }
            }
            __syncthreads();
        }
        if (!tid) { g_pv[b * NCH + c] = bv[0]; g_pi[b * NCH + c] = bi[0]; }
        return;
    }
    // GRU: warp per j, all 8 batches
    __shared__ float as_[BQ * DM];
    for (int i = tid; i < BQ * DM / 4; i += 256)
        ((float4*)as_)[i] = ((const float4*)g_ao)[i];
    __syncthreads();
    int j = (bx - 512) * 8 + (tid >> 5);
    int lane = tid & 31;
    const float4* a4 = (const float4*)as_;
    const float4* wir4 = (const float4*)(g_Wihp + (size_t)j * DM);
    const float4* wiz4 = (const float4*)(g_Wihp + (size_t)(DM + j) * DM);
    const float4* win4 = (const float4*)(g_Wihp + (size_t)(2 * DM + j) * DM);
    const float4* wcr4 = (const float4*)(g_Wchp + (size_t)j * DM);
    const float4* wcz4 = (const float4*)(g_Wchp + (size_t)(DM + j) * DM);
    const float4* wcn4 = (const float4*)(g_Wchp + (size_t)(2 * DM + j) * DM);
    float air[8] = {}, aiz[8] = {}, ain[8] = {}, acr[8] = {}, acz[8] = {}, acn[8] = {};
#pragma unroll
    for (int i = 0; i < 8; i++) {
        int f = i * 32 + lane;
        float4 w1 = wir4[f], w2 = wiz4[f], w3 = win4[f];
        float4 w4c = wcr4[f], w5 = wcz4[f], w6 = wcn4[f];
#pragma unroll
        for (int b = 0; b < 8; b++) {
            float4 a = a4[b * 256 + f];
            air[b] += dot4(w1, a); aiz[b] += dot4(w2, a); ain[b] += dot4(w3, a);
            acr[b] += dot4(w4c, a); acz[b] += dot4(w5, a); acn[b] += dot4(w6, a);
        }
    }
#pragma unroll
    for (int b = 0; b < 8; b++) {
        air[b] = warp_sum(air[b]); aiz[b] = warp_sum(aiz[b]); ain[b] = warp_sum(ain[b]);
        acr[b] = warp_sum(acr[b]); acz[b] = warp_sum(acz[b]); acn[b] = warp_sum(acn[b]);
    }
    if (lane) return;
    float bir = g_bihp[j], biz = g_bihp[DM + j], bin = g_bihp[2 * DM + j];
    float bcr = g_bchp[j], bcz = g_bchp[DM + j], bcn = g_bchp[2 * DM + j];
#pragma unroll
    for (int b = 0; b < 8; b++) {
        float ghr = g_gh[b * 3 * DM + j];
        float ghz = g_gh[b * 3 * DM + DM + j];
        float ghn = g_gh[b * 3 * DM + 2 * DM + j];
        float r = 1.f / (1.f + expf(-(air[b] + bir + ghr + acr[b] + bcr)));
        float z = 1.f / (1.f + expf(-(aiz[b] + biz + ghz + acz[b] + bcz)));
        float n = tanhf(ain[b] + bin + acn[b] + bcn + r * ghn);
        hout[b * DM + j] = (1.f - z) * n + z * h[b * DM + j];
    }
}

// ---------------- last token ----------------
__global__ void k_token(float* __restrict__ out, int t, int steps) {
    if (threadIdx.x < 8) {
        int bb = threadIdx.x;
        float best = g_pv[bb * NCH];
        int bidx = g_pi[bb * NCH];
        for (int c = 1; c < NCH; c++) {
            float v = g_pv[bb * NCH + c];
            if (!(v <= best)) { best = v; bidx = g_pi[bb * NCH + c]; }
        }
        out[bb * steps + t] = (float)bidx;
    }
}

// ---------------- host orchestration ----------------
extern "C" void kernel_launch(void* const* d_in, const int* in_sizes, int n_in,
                              void* d_out, int out_size) {
    const float* hidden  = (const float*)d_in[0];
    const float* context = (const float*)d_in[1];
    const int*   ids     = (const int*)d_in[2];
    int base = (in_sizes[3] == 1) ? 4 : 3;
    const float* vdw = (const float*)d_in[base + 0];
    const float* vdb = (const float*)d_in[base + 1];
    const float* vuw = (const float*)d_in[base + 2];
    const float* ipw = (const float*)d_in[base + 3];
    const float* ipb = (const float*)d_in[base + 4];
    const float* opw = (const float*)d_in[base + 5];
    const float* opb = (const float*)d_in[base + 6];
    const float* pgw = (const float*)d_in[base + 7];
    const float* pgb = (const float*)d_in[base + 8];
    const float* wih = (const float*)d_in[base + 9];
    const float* whh = (const float*)d_in[base + 10];
    const float* wch = (const float*)d_in[base + 11];
    const float* bih = (const float*)d_in[base + 12];
    const float* bhh = (const float*)d_in[base + 13];
    const float* inw = (const float*)d_in[base + 14];
    const float* inb = (const float*)d_in[base + 15];
    float* out = (float*)d_out;
    int steps = out_size / BQ;

    float *hbase, *wihp_p, *wchp_p;
    cudaGetSymbolAddress((void**)&hbase, g_h);
    cudaGetSymbolAddress((void**)&wihp_p, g_Wihp);
    cudaGetSymbolAddress((void**)&wchp_p, g_Wchp);

    k_init<<<32, 256>>>(hidden);
    k_kvgemm<<<dim3(16, 128), 256>>>(context, ipw + 1024 * 1024, ipb + 1024);
    k_prep<<<13, 256>>>(inw, inb, opw, opb, pgw);
    k_prev0<<<1, 256>>>(hidden);
    k_mmAB<<<dim3(8, 24), 256>>>(wih, opw, wihp_p);
    k_mmAB<<<dim3(8, 24), 256>>>(wch, opw, wchp_p);
    k_bias2<<<768, 256>>>(wih, wch, bih, opb);
    k_vw23<<<512, 256>>>();

    const int NVB = (VV + 7) / 8;   // 12535 vocabup blocks
    for (int t = 0; t < steps; t++) {
        float* h_in  = hbase + (t & 1) * BQ * DM;
        float* h_out = hbase + ((t + 1) & 1) * BQ * DM;
        k_hstage<<<577, 256>>>(h_in, ipw, ipb, vdw, vdb, whh, bhh, pgw, out, t, steps);
        k_wide1<<<513 + NVB, 256>>>(vuw, t);
        k_wide2<<<576, 256>>>(ids, t);
        k_avk<<<512, 256>>>();
        k_tail<<<640, 256>>>(h_in, h_out, pgb, t);
    }
    k_token<<<1, 32>>>(out, steps - 1, steps);
}

// round 5
// speedup vs baseline: 1.2225x; 1.0460x over previous
#include <cuda_runtime.h>
#include <math.h>

#define BQ   8
#define DM   1024
#define VV   100279
#define BOTN 512
#define NHD  8
#define HDD  128
#define SS   2048
#define NCH  64
#define CHSZ 1567   // ceil(VV/64)

// ---------------- device scratch ----------------
__device__ float g_K[(size_t)BQ*NHD*SS*HDD];
__device__ float g_V[(size_t)BQ*NHD*SS*HDD];
__device__ float g_h[2*BQ*DM];
__device__ float g_q[BQ*DM];
__device__ float g_attn[BQ*NHD*SS];
__device__ float g_ao[BQ*DM];
__device__ float g_gelu[BQ*BOTN];
__device__ float g_gh[BQ*3*DM];
__device__ float g_logits[(size_t)BQ*VV];
__device__ float g_copy[(size_t)BQ*VV];          // zero-init; self-cleaned
__device__ float g_Wihp[(size_t)3*DM*DM];        // wih @ opw
__device__ float g_Wchp[(size_t)3*DM*DM];        // wch @ opw
__device__ float g_bihp[3*DM];
__device__ float g_bchp[3*DM];
__device__ float g_Vw2[BQ*NHD*SS];
__device__ float g_Vw3[BQ*NHD*SS];
__device__ float g_u[DM];                        // inw^T w3
__device__ float g_w2p[DM];                      // opw^T w2
__device__ float g_w3p[DM];                      // opw^T w3
__device__ float g_c[3];                         // c2=w2.opb, c3=w3.opb, s1=w3.inb
__device__ float g_hpart[BQ];
__device__ float g_pacc2[BQ];
__device__ float g_pacc3[2][BQ];
__device__ float g_pm[BQ*NCH];
__device__ float g_ps[BQ*NCH];
__device__ float g_pv[BQ*NCH];
__device__ int   g_pi[BQ*NCH];

__device__ __forceinline__ float warp_sum(float v) {
#pragma unroll
    for (int o = 16; o; o >>= 1) v += __shfl_down_sync(0xffffffffu, v, o);
    return v;
}
__device__ __forceinline__ float dot4(float4 a, float4 b) {
    return a.x*b.x + a.y*b.y + a.z*b.z + a.w*b.w;
}

// ---------------- init ----------------
__global__ void k_init(const float* __restrict__ hs) {
    int i = blockIdx.x * blockDim.x + threadIdx.x;
    if (i < BQ * DM) g_h[i] = hs[i];
}

// ---------------- one-time K/V projection GEMM (A@W^T + bias) ----------------
__global__ void k_kvgemm(const float* __restrict__ A, const float* __restrict__ W,
                         const float* __restrict__ bias) {
    __shared__ float As[16][128];
    __shared__ float Bs[16][128];
    int tid = threadIdx.x;
    int bm = blockIdx.y * 128, bn = blockIdx.x * 128;
    int tr = tid >> 4, tc = tid & 15;
    float acc[8][8];
#pragma unroll
    for (int i = 0; i < 8; i++)
#pragma unroll
        for (int j = 0; j < 8; j++) acc[i][j] = 0.f;
    int lr = tid >> 2;
    int lk = (tid & 3) * 4;
    const float* Ag = A + (size_t)(bm + lr) * DM + lk;
    const float* Wg = W + (size_t)(bn + lr) * DM + lk;
    for (int kt = 0; kt < DM; kt += 16) {
        float4 a0 = *(const float4*)(Ag + kt);
        float4 a1 = *(const float4*)(Ag + (size_t)64 * DM + kt);
        float4 b0 = *(const float4*)(Wg + kt);
        float4 b1 = *(const float4*)(Wg + (size_t)64 * DM + kt);
        As[lk+0][lr] = a0.x; As[lk+1][lr] = a0.y; As[lk+2][lr] = a0.z; As[lk+3][lr] = a0.w;
        As[lk+0][lr+64] = a1.x; As[lk+1][lr+64] = a1.y; As[lk+2][lr+64] = a1.z; As[lk+3][lr+64] = a1.w;
        Bs[lk+0][lr] = b0.x; Bs[lk+1][lr] = b0.y; Bs[lk+2][lr] = b0.z; Bs[lk+3][lr] = b0.w;
        Bs[lk+0][lr+64] = b1.x; Bs[lk+1][lr+64] = b1.y; Bs[lk+2][lr+64] = b1.z; Bs[lk+3][lr+64] = b1.w;
        __syncthreads();
#pragma unroll
        for (int kk = 0; kk < 16; kk++) {
            float ra[8], rb[8];
#pragma unroll
            for (int i = 0; i < 8; i++) ra[i] = As[kk][tr + 16 * i];
#pragma unroll
            for (int j = 0; j < 8; j++) rb[j] = Bs[kk][tc + 16 * j];
#pragma unroll
            for (int i = 0; i < 8; i++)
#pragma unroll
                for (int j = 0; j < 8; j++) acc[i][j] += ra[i] * rb[j];
        }
        __syncthreads();
    }
#pragma unroll
    for (int i = 0; i < 8; i++) {
        int m = bm + tr + 16 * i;
        int b = m >> 11, s = m & 2047;
#pragma unroll
        for (int j = 0; j < 8; j++) {
            int n = bn + tc + 16 * j;
            float val = acc[i][j] + bias[n];
            if (n < DM)
                g_K[((size_t)(b * NHD + (n >> 7)) * SS + s) * HDD + (n & 127)] = val;
            else {
                int n2 = n - DM;
                g_V[((size_t)(b * NHD + (n2 >> 7)) * SS + s) * HDD + (n2 & 127)] = val;
            }
        }
    }
}

// ---------------- one-time C = A @ B (A[M,1024], B[1024,1024]) ----------------
__global__ void k_mmAB(const float* __restrict__ A, const float* __restrict__ B,
                       float* __restrict__ C) {
    __shared__ float As[16][128];
    __shared__ float Bs[16][128];
    int tid = threadIdx.x;
    int bm = blockIdx.y * 128, bn = blockIdx.x * 128;
    int tr = tid >> 4, tc = tid & 15;
    float acc[8][8];
#pragma unroll
    for (int i = 0; i < 8; i++)
#pragma unroll
        for (int j = 0; j < 8; j++) acc[i][j] = 0.f;
    int lr = tid >> 2;
    int lk = (tid & 3) * 4;
    int bkr = tid >> 4;            // 0..15
    int bnc = (tid & 15) * 4;      // 0..60
    const float* Ag = A + (size_t)(bm + lr) * DM + lk;
    for (int kt = 0; kt < DM; kt += 16) {
        float4 a0 = *(const float4*)(Ag + kt);
        float4 a1 = *(const float4*)(Ag + (size_t)64 * DM + kt);
        As[lk+0][lr] = a0.x; As[lk+1][lr] = a0.y; As[lk+2][lr] = a0.z; As[lk+3][lr] = a0.w;
        As[lk+0][lr+64] = a1.x; As[lk+1][lr+64] = a1.y; As[lk+2][lr+64] = a1.z; As[lk+3][lr+64] = a1.w;
        float4 b0 = *(const float4*)(B + (size_t)(kt + bkr) * DM + bn + bnc);
        float4 b1 = *(const float4*)(B + (size_t)(kt + bkr) * DM + bn + bnc + 64);
        Bs[bkr][bnc+0] = b0.x; Bs[bkr][bnc+1] = b0.y; Bs[bkr][bnc+2] = b0.z; Bs[bkr][bnc+3] = b0.w;
        Bs[bkr][bnc+64] = b1.x; Bs[bkr][bnc+65] = b1.y; Bs[bkr][bnc+66] = b1.z; Bs[bkr][bnc+67] = b1.w;
        __syncthreads();
#pragma unroll
        for (int kk = 0; kk < 16; kk++) {
            float ra[8], rb[8];
#pragma unroll
            for (int i = 0; i < 8; i++) ra[i] = As[kk][tr + 16 * i];
#pragma unroll
            for (int j = 0; j < 8; j++) rb[j] = Bs[kk][tc + 16 * j];
#pragma unroll
            for (int i = 0; i < 8; i++)
#pragma unroll
                for (int j = 0; j < 8; j++) acc[i][j] += ra[i] * rb[j];
        }
        __syncthreads();
    }
#pragma unroll
    for (int i = 0; i < 8; i++)
#pragma unroll
        for (int j = 0; j < 8; j++)
            C[(size_t)(bm + tr + 16 * i) * DM + bn + tc + 16 * j] = acc[i][j];
}

// ---------------- one-time: u = inw^T w3, w2p = opw^T w2, w3p = opw^T w3, scalars ----
__global__ void k_prep(const float* __restrict__ inw, const float* __restrict__ inb,
                       const float* __restrict__ opw, const float* __restrict__ opb,
                       const float* __restrict__ pgw) {
    int blk = blockIdx.x, tid = threadIdx.x;
    if (blk < 12) {
        int which = blk >> 2;                 // 0:u 1:w2p 2:w3p
        int d = (blk & 3) * 256 + tid;
        const float* Wm = which ? opw : inw;
        const float* vec = (which == 1) ? pgw + DM : pgw + 2 * DM;
        float acc = 0.f;
        for (int k = 0; k < DM; k++) acc += vec[k] * Wm[(size_t)k * DM + d];
        if (which == 0) g_u[d] = acc;
        else if (which == 1) g_w2p[d] = acc;
        else g_w3p[d] = acc;
    } else {
        int w = tid >> 5, lane = tid & 31;
        if (w < 3) {
            const float* vec = (w == 0) ? pgw + DM : pgw + 2 * DM;
            const float* src = (w == 2) ? inb : opb;
            float acc = 0.f;
            for (int k = lane; k < DM; k += 32) acc += vec[k] * src[k];
            acc = warp_sum(acc);
            if (!lane) g_c[w] = acc;          // c2, c3, s1
        }
    }
}

// ---------------- one-time: prev0 partial -> pacc3[1] ----------------
__global__ void k_prev0(const float* __restrict__ h0) {
    int w = threadIdx.x >> 5, lane = threadIdx.x & 31;
    if (w < 8) {
        float acc = 0.f;
        for (int d = lane; d < DM; d += 32) acc += h0[w * DM + d] * g_u[d];
        acc = warp_sum(acc);
        if (!lane) g_pacc3[1][w] = acc + g_c[2] - g_c[1];   // prev0.w3 - c3
    }
}

// ---------------- one-time: bihp/bchp ----------------
__global__ void k_bias2(const float* __restrict__ wih, const float* __restrict__ wch,
                        const float* __restrict__ bih, const float* __restrict__ opb) {
    int w = (blockIdx.x * 256 + threadIdx.x) >> 5, lane = threadIdx.x & 31;
    if (w >= 6144) return;
    int type = w >= 3072 ? 1 : 0;
    int j = w - type * 3072;
    const float* row = (type ? wch : wih) + (size_t)j * DM;
    float acc = 0.f;
    for (int d = lane; d < DM; d += 32) acc += row[d] * opb[d];
    acc = warp_sum(acc);
    if (!lane) { if (type) g_bchp[j] = acc; else g_bihp[j] = acc + bih[j]; }
}

// ---------------- one-time: Vw2/Vw3 ----------------
__global__ void k_vw23() {
    int gw = (blockIdx.x * 256 + threadIdx.x) >> 5, lane = threadIdx.x & 31;
    int r0 = gw * 32;
    for (int rr = 0; rr < 32; rr++) {
        int r = r0 + rr;                        // [0, 131072)
        int h = (r >> 11) & 7;
        float4 a  = ((const float4*)(g_V + (size_t)r * HDD))[lane];
        float4 w2 = *(const float4*)(g_w2p + h * HDD + lane * 4);
        float4 w3 = *(const float4*)(g_w3p + h * HDD + lane * 4);
        float d2 = warp_sum(dot4(a, w2));
        float d3 = warp_sum(dot4(a, w3));
        if (!lane) { g_Vw2[r] = d2; g_Vw3[r] = d3; }
    }
}

// ---------------- L1: q, gelu, gh, hpart from h (+ token combine t-1) ----------
__global__ void k_hstage(const float* __restrict__ h,
                         const float* __restrict__ ipw, const float* __restrict__ ipb,
                         const float* __restrict__ vdw, const float* __restrict__ vdb,
                         const float* __restrict__ whh, const float* __restrict__ bhh,
                         const float* __restrict__ pgw,
                         float* __restrict__ out, int t, int steps) {
    __shared__ float hs[BQ * DM];
    int tid = threadIdx.x;
    if (blockIdx.x == 0 && tid < 8 && t > 0) {
        int bb = tid;
        float best = g_pv[bb * NCH];
        int bidx = g_pi[bb * NCH];
        for (int c = 1; c < NCH; c++) {
            float v = g_pv[bb * NCH + c];
            if (!(v <= best)) { best = v; bidx = g_pi[bb * NCH + c]; }
        }
        out[bb * steps + (t - 1)] = (float)bidx;
    }
    for (int i = tid; i < BQ * DM / 4; i += 256)
        ((float4*)hs)[i] = ((const float4*)h)[i];
    __syncthreads();
    int job = blockIdx.x * 8 + (tid >> 5);
    int lane = tid & 31;
    if (job >= 4609) return;
    const float* wrow;
    if (job < 1024)       wrow = ipw + (size_t)job * DM;
    else if (job < 1536)  wrow = vdw + (size_t)(job - 1024) * DM;
    else if (job < 4608)  wrow = whh + (size_t)(job - 1536) * DM;
    else                  wrow = pgw;
    const float4* w4p = (const float4*)wrow;
    const float4* h4 = (const float4*)hs;
    float acc[8] = {};
#pragma unroll
    for (int i = 0; i < 8; i++) {
        int f = i * 32 + lane;
        float4 w4 = w4p[f];
#pragma unroll
        for (int b = 0; b < 8; b++) {
            float4 a4 = h4[b * 256 + f];
            acc[b] += dot4(w4, a4);
        }
    }
#pragma unroll
    for (int b = 0; b < 8; b++) acc[b] = warp_sum(acc[b]);
    if (lane) return;
    if (job < 1024) {
        float bias = ipb[job];
#pragma unroll
        for (int b = 0; b < 8; b++) g_q[b * DM + job] = acc[b] + bias;
    } else if (job < 1536) {
        int j = job - 1024;
        float bias = vdb[j];
#pragma unroll
        for (int b = 0; b < 8; b++) {
            float x = acc[b] + bias;
            g_gelu[b * BOTN + j] = 0.5f * x * (1.f + erff(x * 0.70710678118654752f));
        }
    } else if (job < 4608) {
        int j = job - 1536;
        float bias = bhh[j];
#pragma unroll
        for (int b = 0; b < 8; b++) g_gh[b * 3 * DM + j] = acc[b] + bias;
    } else {
#pragma unroll
        for (int b = 0; b < 8; b++) g_hpart[b] = acc[b];
    }
}

// ---------------- L2: scores + zero + vocabup ----------------
__global__ void k_wide1(const float* __restrict__ vuw, int t) {
    int bx = blockIdx.x, tid = threadIdx.x;
    if (bx < 512) {
        int b = bx >> 6, hh = (bx >> 3) & 7, ch = bx & 7;
        int warp = tid >> 5, lane = tid & 31;
        float4 q4 = *(const float4*)(g_q + b * DM + hh * HDD + lane * 4);
        int bh = b * 8 + hh;
        const float4* K4 = (const float4*)(g_K + (size_t)bh * SS * HDD);
        int s0 = ch * 256 + warp * 32;
#pragma unroll 4
        for (int ss = 0; ss < 32; ss++) {
            int s = s0 + ss;
            float d = warp_sum(dot4(K4[s * 32 + lane], q4));
            if (!lane) g_attn[bh * SS + s] = d * 0.08838834764831845f;
        }
        return;
    }
    if (bx == 512) {
        for (int i = tid; i < BQ * DM; i += 256) g_ao[i] = 0.f;
        if (tid < 8) { g_pacc2[tid] = 0.f; g_pacc3[t & 1][tid] = 0.f; }
        return;
    }
    __shared__ float gs[BQ * BOTN];
    for (int i = tid; i < BQ * BOTN / 4; i += 256)
        ((float4*)gs)[i] = ((const float4*)g_gelu)[i];
    __syncthreads();
    int v = (bx - 513) * 8 + (tid >> 5);
    int lane = tid & 31;
    if (v >= VV) return;
    const float4* w4p = (const float4*)(vuw + (size_t)v * BOTN);
    const float4* g4 = (const float4*)gs;
    float4 acc4[8];
#pragma unroll
    for (int b = 0; b < 8; b++) acc4[b] = make_float4(0.f, 0.f, 0.f, 0.f);
#pragma unroll
    for (int i = 0; i < 4; i++) {
        int f = i * 32 + lane;
        float4 w4 = w4p[f];
#pragma unroll
        for (int b = 0; b < 8; b++) {
            float4 a4 = g4[b * 128 + f];
            acc4[b].x += w4.x * a4.x; acc4[b].y += w4.y * a4.y;
            acc4[b].z += w4.z * a4.z; acc4[b].w += w4.w * a4.w;
        }
    }
#pragma unroll
    for (int b = 0; b < 8; b++) {
        float s = warp_sum(acc4[b].x + acc4[b].y + acc4[b].z + acc4[b].w);
        if (!lane) g_logits[(size_t)b * VV + v] = s;
    }
}

// ---------------- L3: softmax+scatter+pgen dots  |  logit stats chunks ----------
__global__ void k_wide2(const int* __restrict__ ids, int t) {
    __shared__ float sm[SS];
    __shared__ float red[256];
    int bx = blockIdx.x, tid = threadIdx.x;
    if (bx < 64) {
        int bh = bx, b = bh >> 3;
        float* row = g_attn + (size_t)bh * SS;
        float m = -INFINITY;
        for (int s = tid; s < SS; s += 256) { float v = row[s]; sm[s] = v; m = fmaxf(m, v); }
        red[tid] = m; __syncthreads();
        for (int o = 128; o; o >>= 1) { if (tid < o) red[tid] = fmaxf(red[tid], red[tid + o]); __syncthreads(); }
        m = red[0]; __syncthreads();
        float sum = 0.f;
        for (int s = tid; s < SS; s += 256) { float e = expf(sm[s] - m); sm[s] = e; sum += e; }
        red[tid] = sum; __syncthreads();
        for (int o = 128; o; o >>= 1) { if (tid < o) red[tid] += red[tid + o]; __syncthreads(); }
        float inv = 1.f / red[0];
        __syncthreads();
        const int* idr = ids + b * SS;
        float acc2 = 0.f, acc3 = 0.f;
        for (int s = tid; s < SS; s += 256) {
            float p = sm[s] * inv;
            row[s] = p;
            acc2 += p * g_Vw2[bh * SS + s];
            acc3 += p * g_Vw3[bh * SS + s];
            int id = idr[s];
            if (id >= 0) atomicAdd(&g_copy[(size_t)b * VV + id], p * 0.125f);
        }
        red[tid] = acc2; __syncthreads();
        for (int o = 128; o; o >>= 1) { if (tid < o) red[tid] += red[tid + o]; __syncthreads(); }
        if (!tid) atomicAdd(&g_pacc2[b], red[0]);
        __syncthreads();
        red[tid] = acc3; __syncthreads();
        for (int o = 128; o; o >>= 1) { if (tid < o) red[tid] += red[tid + o]; __syncthreads(); }
        if (!tid) atomicAdd(&g_pacc3[t & 1][b], red[0]);
        return;
    }
    int cc = bx - 64;
    int b = cc >> 6, c = cc & 63;
    int start = c * CHSZ, end = min(start + CHSZ, VV);
    const float* lr = g_logits + (size_t)b * VV;
    float m = -INFINITY;
    for (int i = start + tid; i < end; i += 256) m = fmaxf(m, lr[i]);
    red[tid] = m; __syncthreads();
    for (int o = 128; o; o >>= 1) { if (tid < o) red[tid] = fmaxf(red[tid], red[tid + o]); __syncthreads(); }
    m = red[0]; __syncthreads();
    float sum = 0.f;
    for (int i = start + tid; i < end; i += 256) sum += expf(lr[i] - m);
    red[tid] = sum; __syncthreads();
    for (int o = 128; o; o >>= 1) { if (tid < o) red[tid] += red[tid + o]; __syncthreads(); }
    if (!tid) { g_pm[b * NCH + c] = m; g_ps[b * NCH + c] = red[0]; }
}

// ---------------- L4: attn @ V -> ao ----------------
__global__ void k_avk() {
    __shared__ float sa[256];
    __shared__ float sacc[8 * 128];
    int bx = blockIdx.x, tid = threadIdx.x;
    int b = bx >> 6, hh = (bx >> 3) & 7, ch = bx & 7, bh = b * 8 + hh;
    sa[tid] = g_attn[bh * SS + ch * 256 + tid];
    __syncthreads();
    int warp = tid >> 5, lane = tid & 31;
    const float4* V4 = (const float4*)(g_V + (size_t)bh * SS * HDD);
    float4 acc = make_float4(0.f, 0.f, 0.f, 0.f);
    int s0 = ch * 256 + warp * 32;
#pragma unroll 4
    for (int ss = 0; ss < 32; ss++) {
        float a = sa[warp * 32 + ss];
        float4 v4 = V4[(s0 + ss) * 32 + lane];
        acc.x += a * v4.x; acc.y += a * v4.y; acc.z += a * v4.z; acc.w += a * v4.w;
    }
    float* strip = sacc + warp * 128 + lane * 4;
    strip[0] = acc.x; strip[1] = acc.y; strip[2] = acc.z; strip[3] = acc.w;
    __syncthreads();
    if (tid < 128) {
        float s = 0.f;
#pragma unroll
        for (int w = 0; w < 8; w++) s += sacc[w * 128 + tid];
        atomicAdd(&g_ao[b * DM + hh * HDD + tid], s);
    }
}

// ---------------- L5: final argmax (+pgen inline)  |  GRU ----------------
__global__ void k_tail(const float* __restrict__ h, float* __restrict__ hout,
                       const float* __restrict__ pgb, int t) {
    int bx = blockIdx.x, tid = threadIdx.x;
    if (bx < 512) {
        __shared__ float spm[NCH], sps[NCH], sMZ[2];
        __shared__ float bv[256];
        __shared__ int bi[256];
        int b = bx >> 6, c = bx & 63;
        if (tid < NCH) { spm[tid] = g_pm[b * NCH + tid]; sps[tid] = g_ps[b * NCH + tid]; }
        __syncthreads();
        if (!tid) {
            float M = -INFINITY;
            for (int i = 0; i < NCH; i++) M = fmaxf(M, spm[i]);
            float Z = 0.f;
            for (int i = 0; i < NCH; i++) Z += sps[i] * expf(spm[i] - M);
            sMZ[0] = M; sMZ[1] = Z;
        }
        __syncthreads();
        float M = sMZ[0];
        float pg = 1.f / (1.f + expf(-(g_hpart[b] + g_pacc2[b] + g_c[0]
                                       + g_pacc3[(t + 1) & 1][b] + g_c[1] + pgb[0])));
        float a = pg / sMZ[1];
        float om = 1.f - pg;
        int start = c * CHSZ, end = min(start + CHSZ, VV);
        float* lr = g_logits + (size_t)b * VV;
        float* cr = g_copy + (size_t)b * VV;
        float best = -INFINITY; int bidx = start;
        for (int i = start + tid; i < end; i += 256) {
            float f = a * expf(lr[i] - M) + om * cr[i];
            cr[i] = 0.f;
            if (!(f <= best)) { best = f; bidx = i; }
        }
        bv[tid] = best; bi[tid] = bidx; __syncthreads();
        for (int o = 128; o; o >>= 1) {
            if (tid < o) {
                float v2 = bv[tid + o]; int i2 = bi[tid + o];
                if (!(v2 <= bv[tid]) || (v2 == bv[tid] && i2 < bi[tid])) { bv[tid] = v2; bi[tid] = i2; }
            }
            __syncthreads();
        }
        if (!tid) { g_pv[b * NCH + c] = bv[0]; g_pi[b * NCH + c] = bi[0]; }
        return;
    }
    // GRU: warp per j, all 8 batches
    __shared__ float as_[BQ * DM];
    for (int i = tid; i < BQ * DM / 4; i += 256)
        ((float4*)as_)[i] = ((const float4*)g_ao)[i];
    __syncthreads();
    int j = (bx - 512) * 8 + (tid >> 5);
    int lane = tid & 31;
    const float4* a4 = (const float4*)as_;
    const float4* wir4 = (const float4*)(g_Wihp + (size_t)j * DM);
    const float4* wiz4 = (const float4*)(g_Wihp + (size_t)(DM + j) * DM);
    const float4* win4 = (const float4*)(g_Wihp + (size_t)(2 * DM + j) * DM);
    const float4* wcr4 = (const float4*)(g_Wchp + (size_t)j * DM);
    const float4* wcz4 = (const float4*)(g_Wchp + (size_t)(DM + j) * DM);
    const float4* wcn4 = (const float4*)(g_Wchp + (size_t)(2 * DM + j) * DM);
    float air[8] = {}, aiz[8] = {}, ain[8] = {}, acr[8] = {}, acz[8] = {}, acn[8] = {};
#pragma unroll
    for (int i = 0; i < 8; i++) {
        int f = i * 32 + lane;
        float4 w1 = wir4[f], w2 = wiz4[f], w3 = win4[f];
        float4 w4c = wcr4[f], w5 = wcz4[f], w6 = wcn4[f];
#pragma unroll
        for (int b = 0; b < 8; b++) {
            float4 a = a4[b * 256 + f];
            air[b] += dot4(w1, a); aiz[b] += dot4(w2, a); ain[b] += dot4(w3, a);
            acr[b] += dot4(w4c, a); acz[b] += dot4(w5, a); acn[b] += dot4(w6, a);
        }
    }
#pragma unroll
    for (int b = 0; b < 8; b++) {
        air[b] = warp_sum(air[b]); aiz[b] = warp_sum(aiz[b]); ain[b] = warp_sum(ain[b]);
        acr[b] = warp_sum(acr[b]); acz[b] = warp_sum(acz[b]); acn[b] = warp_sum(acn[b]);
    }
    if (lane) return;
    float bir = g_bihp[j], biz = g_bihp[DM + j], bin = g_bihp[2 * DM + j];
    float bcr = g_bchp[j], bcz = g_bchp[DM + j], bcn = g_bchp[2 * DM + j];
#pragma unroll
    for (int b = 0; b < 8; b++) {
        float ghr = g_gh[b * 3 * DM + j];
        float ghz = g_gh[b * 3 * DM + DM + j];
        float ghn = g_gh[b * 3 * DM + 2 * DM + j];
        float r = 1.f / (1.f + expf(-(air[b] + bir + ghr + acr[b] + bcr)));
        float z = 1.f / (1.f + expf(-(aiz[b] + biz + ghz + acz[b] + bcz)));
        float n = tanhf(ain[b] + bin + acn[b] + bcn + r * ghn);
        hout[b * DM + j] = (1.f - z) * n + z * h[b * DM + j];
    }
}

// ---------------- last token ----------------
__global__ void k_token(float* __restrict__ out, int t, int steps) {
    if (threadIdx.x < 8) {
        int bb = threadIdx.x;
        float best = g_pv[bb * NCH];
        int bidx = g_pi[bb * NCH];
        for (int c = 1; c < NCH; c++) {
            float v = g_pv[bb * NCH + c];
            if (!(v <= best)) { best = v; bidx = g_pi[bb * NCH + c]; }
        }
        out[bb * steps + t] = (float)bidx;
    }
}

// ---------------- host orchestration ----------------
extern "C" void kernel_launch(void* const* d_in, const int* in_sizes, int n_in,
                              void* d_out, int out_size) {
    const float* hidden  = (const float*)d_in[0];
    const float* context = (const float*)d_in[1];
    const int*   ids     = (const int*)d_in[2];
    int base = (in_sizes[3] == 1) ? 4 : 3;
    const float* vdw = (const float*)d_in[base + 0];
    const float* vdb = (const float*)d_in[base + 1];
    const float* vuw = (const float*)d_in[base + 2];
    const float* ipw = (const float*)d_in[base + 3];
    const float* ipb = (const float*)d_in[base + 4];
    const float* opw = (const float*)d_in[base + 5];
    const float* opb = (const float*)d_in[base + 6];
    const float* pgw = (const float*)d_in[base + 7];
    const float* pgb = (const float*)d_in[base + 8];
    const float* wih = (const float*)d_in[base + 9];
    const float* whh = (const float*)d_in[base + 10];
    const float* wch = (const float*)d_in[base + 11];
    const float* bih = (const float*)d_in[base + 12];
    const float* bhh = (const float*)d_in[base + 13];
    const float* inw = (const float*)d_in[base + 14];
    const float* inb = (const float*)d_in[base + 15];
    float* out = (float*)d_out;
    int steps = out_size / BQ;

    float *hbase, *wihp_p, *wchp_p;
    cudaGetSymbolAddress((void**)&hbase, g_h);
    cudaGetSymbolAddress((void**)&wihp_p, g_Wihp);
    cudaGetSymbolAddress((void**)&wchp_p, g_Wchp);

    k_init<<<32, 256>>>(hidden);
    k_kvgemm<<<dim3(16, 128), 256>>>(context, ipw + 1024 * 1024, ipb + 1024);
    k_prep<<<13, 256>>>(inw, inb, opw, opb, pgw);
    k_prev0<<<1, 256>>>(hidden);
    k_mmAB<<<dim3(8, 24), 256>>>(wih, opw, wihp_p);
    k_mmAB<<<dim3(8, 24), 256>>>(wch, opw, wchp_p);
    k_bias2<<<768, 256>>>(wih, wch, bih, opb);
    k_vw23<<<512, 256>>>();

    const int NVB = (VV + 7) / 8;   // 12535 vocabup blocks
    for (int t = 0; t < steps; t++) {
        float* h_in  = hbase + (t & 1) * BQ * DM;
        float* h_out = hbase + ((t + 1) & 1) * BQ * DM;
        k_hstage<<<577, 256>>>(h_in, ipw, ipb, vdw, vdb, whh, bhh, pgw, out, t, steps);
        k_wide1<<<513 + NVB, 256>>>(vuw, t);
        k_wide2<<<576, 256>>>(ids, t);
        k_avk<<<512, 256>>>();
        k_tail<<<640, 256>>>(h_in, h_out, pgb, t);
    }
    k_token<<<1, 32>>>(out, steps - 1, steps);
}